// round 17
// baseline (speedup 1.0000x reference)
#include <cuda_runtime.h>
#include <stdint.h>
#include <math.h>

#define Bb 2
#define Hh 16
#define Ss 2048
#define Dd 64

__device__ float g_invl[Bb * Hh * Ss];

#define LDE 72                 // padded K/V smem row length (fp16 elems)
#define ROWB (LDE * 2)         // 144 bytes per row
// kernel A smem: Q plane, K plane, mask
#define A_OFF_Q 0
#define A_OFF_K (A_OFF_Q + 128 * ROWB)
#define A_OFF_MASK (A_OFF_K + 128 * ROWB)
#define A_SMEM (A_OFF_MASK + 512)
// kernel B smem: e plane (fp16 words, padded) + V plane
#define EROWB 272              // 64 data words + 4 pad words (stride % 128B == 16B)
#define OFF_E 0
#define OFF_V (OFF_E + 128 * EROWB)
#define B_SMEM (OFF_V + 128 * ROWB)

__device__ __forceinline__ uint32_t smem_u32(const void* p) {
    uint32_t a;
    asm("{ .reg .u64 t; cvta.to.shared.u64 t, %1; cvt.u32.u64 %0, t; }" : "=r"(a) : "l"(p));
    return a;
}
__device__ __forceinline__ uint32_t pack16(float a, float b) {
    uint32_t r;
    asm("cvt.rn.f16x2.f32 %0, %1, %2;" : "=r"(r) : "f"(b), "f"(a));
    return r;
}
__device__ __forceinline__ float2 unpack16(uint32_t w) {
    float2 f;
    asm("{ .reg .b16 x,y; mov.b32 {x,y}, %2; cvt.f32.f16 %0, x; cvt.f32.f16 %1, y; }"
        : "=f"(f.x), "=f"(f.y) : "r"(w));
    return f;
}
__device__ __forceinline__ void ldsm4(uint32_t (&r)[4], uint32_t a) {
    asm volatile("ldmatrix.sync.aligned.m8n8.x4.shared.b16 {%0,%1,%2,%3}, [%4];"
                 : "=r"(r[0]), "=r"(r[1]), "=r"(r[2]), "=r"(r[3]) : "r"(a));
}
__device__ __forceinline__ void ldsm4t(uint32_t& r0, uint32_t& r1, uint32_t& r2, uint32_t& r3,
                                       uint32_t a) {
    asm volatile("ldmatrix.sync.aligned.m8n8.x4.trans.shared.b16 {%0,%1,%2,%3}, [%4];"
                 : "=r"(r0), "=r"(r1), "=r"(r2), "=r"(r3) : "r"(a));
}
__device__ __forceinline__ void mma16816(float (&c)[4], const uint32_t (&a)[4],
                                         uint32_t b0, uint32_t b1) {
    asm volatile("mma.sync.aligned.m16n8k16.row.col.f32.f16.f16.f32 "
                 "{%0,%1,%2,%3}, {%4,%5,%6,%7}, {%8,%9}, {%0,%1,%2,%3};"
                 : "+f"(c[0]), "+f"(c[1]), "+f"(c[2]), "+f"(c[3])
                 : "r"(a[0]), "r"(a[1]), "r"(a[2]), "r"(a[3]), "r"(b0), "r"(b1));
}
__device__ __forceinline__ void prefetchL2(const void* p) {
    asm volatile("prefetch.global.L2 [%0];" ::"l"(p));
}
__device__ __forceinline__ void stcs2(float* p, float2 v) {
    asm volatile("st.global.cs.v2.f32 [%0], {%1,%2};" ::"l"(p), "f"(v.x), "f"(v.y));
}
__device__ __forceinline__ void stcs4(float* p, float4 v) {
    asm volatile("st.global.cs.v4.f32 [%0], {%1,%2,%3,%4};"
                 ::"l"(p), "f"(v.x), "f"(v.y), "f"(v.z), "f"(v.w));
}

// Quad-local repack: lo_pair = row cols kb+2t..+1, hi_pair = cols kb+8+2t..+1.
// Returns float4 = cols kb+4t .. kb+4t+3 (contiguous) via 2-round butterfly.
__device__ __forceinline__ float4 repack4(float2 lo_pair, float2 hi_pair, int t) {
    float2 z = (t < 2) ? hi_pair : lo_pair;
    float2 r;
    r.x = __shfl_xor_sync(0xffffffffu, z.x, 2);
    r.y = __shfl_xor_sync(0xffffffffu, z.y, 2);
    float2 o = (t < 2) ? lo_pair : hi_pair;
    bool selr = (t == 0) || (t == 3);
    float2 s = selr ? r : o;
    float2 sr;
    sr.x = __shfl_xor_sync(0xffffffffu, s.x, 1);
    sr.y = __shfl_xor_sync(0xffffffffu, s.y, 1);
    float2 lo4, hi4;
    if (t == 0)      { lo4 = o;  hi4 = sr; }
    else if (t == 1) { lo4 = sr; hi4 = r;  }
    else if (t == 2) { lo4 = r;  hi4 = sr; }
    else             { lo4 = sr; hi4 = o;  }
    return make_float4(lo4.x, lo4.y, hi4.x, hi4.y);
}

// ===== Kernel A: row sums + fp16 e scratch (into att rows' first half) =====
__global__ __launch_bounds__(256, 4)
void attn_sums(const float* __restrict__ Q, const float* __restrict__ K,
               const int* __restrict__ M, float* __restrict__ att)
{
    const int bid = blockIdx.x;
    const int tid = threadIdx.x;
    extern __shared__ char smc[];
    const uint32_t smb = smem_u32(smc);
    const int w = tid >> 5;
    const int lane = tid & 31;
    const int g = lane >> 2;
    const int t = lane & 3;
    const int l15 = lane & 15;

    const int bh = bid >> 4;
    const int b = bh / Hh;
    const int q0 = (bid & 15) * 128;

    const float* Qg = Q + ((size_t)bh * Ss + q0) * Dd;
    const float* Kg = K + (size_t)bh * Ss * Dd;
    const int* Mg = M + (size_t)b * Ss;
    uint32_t* WA = (uint32_t*)(att + (size_t)bh * Ss * Ss);  // word view of this bh's att
    float* maskS = (float*)(smc + A_OFF_MASK);

    for (int i = tid; i < 2048; i += 256) {
        int row = i >> 4;
        int d4 = (i & 15) << 2;
        float4 v = *(const float4*)(Qg + (size_t)row * Dd + d4);
        v.x *= 0.125f; v.y *= 0.125f; v.z *= 0.125f; v.w *= 0.125f;
        *(uint2*)(smc + A_OFF_Q + row * ROWB + d4 * 2) =
            make_uint2(pack16(v.x, v.y), pack16(v.z, v.w));
    }
    __syncthreads();

    uint32_t qh[4][4];
    {
        uint32_t abase = smb + (uint32_t)(w * 16 + l15) * ROWB + ((lane >> 4) * 8) * 2;
        #pragma unroll
        for (int ks = 0; ks < 4; ++ks)
            ldsm4(qh[ks], abase + A_OFF_Q + ks * 32);
    }
    const uint32_t kaddr = smb + A_OFF_K +
        (uint32_t)((lane & 7) + ((lane >> 4) & 1) * 8) * ROWB + ((lane >> 3) & 1) * 16;

    const int r0 = q0 + w * 16 + g;
    float lp0 = 0.f, lp1 = 0.f;
    for (int kt = 0; kt < Ss / 128; ++kt) {
        const int k0 = kt * 128;
        __syncthreads();
        for (int i = tid; i < 2048; i += 256) {
            int row = i >> 4;
            int d4 = (i & 15) << 2;
            float4 v = *(const float4*)(Kg + (size_t)(k0 + row) * Dd + d4);
            *(uint2*)(smc + A_OFF_K + row * ROWB + d4 * 2) =
                make_uint2(pack16(v.x, v.y), pack16(v.z, v.w));
        }
        if (tid < 128) maskS[tid] = Mg[k0 + tid] ? 0.f : 1.f;
        if (kt + 1 < Ss / 128)
            prefetchL2(Kg + (size_t)(k0 + 128) * Dd + tid * 32);
        __syncthreads();

        for (int ch = 0; ch < 8; ++ch) {
            const int kb = ch * 16;
            float s0[4] = {0.f, 0.f, 0.f, 0.f};
            float s1[4] = {0.f, 0.f, 0.f, 0.f};
            const uint32_t ka = kaddr + (uint32_t)kb * ROWB;
            #pragma unroll
            for (int ks = 0; ks < 4; ++ks) {
                uint32_t kr[4];
                ldsm4(kr, ka + ks * 32);
                mma16816(s0, qh[ks], kr[0], kr[1]);
                mma16816(s1, qh[ks], kr[2], kr[3]);
            }
            float m00 = maskS[kb + 2 * t];
            float m01 = maskS[kb + 2 * t + 1];
            float m10 = maskS[kb + 8 + 2 * t];
            float m11 = maskS[kb + 8 + 2 * t + 1];
            float e00 = m00 * __expf(s0[0]);
            float e01 = m01 * __expf(s0[1]);
            float e02 = m00 * __expf(s0[2]);
            float e03 = m01 * __expf(s0[3]);
            float e10 = m10 * __expf(s1[0]);
            float e11 = m11 * __expf(s1[1]);
            float e12 = m10 * __expf(s1[2]);
            float e13 = m11 * __expf(s1[3]);
            lp0 += (e00 + e01) + (e10 + e11);
            lp1 += (e02 + e03) + (e12 + e13);

            // fp16 e scratch: word j of row r covers cols 2j,2j+1 (first 4KB of row)
            size_t wb0 = (size_t)r0 * 2048 + (size_t)((k0 + kb) >> 1);
            size_t wb1 = wb0 + 8 * 2048;
            WA[wb0 + t]     = pack16(e00, e01);
            WA[wb0 + 4 + t] = pack16(e10, e11);
            WA[wb1 + t]     = pack16(e02, e03);
            WA[wb1 + 4 + t] = pack16(e12, e13);
        }
    }
    lp0 += __shfl_xor_sync(0xffffffffu, lp0, 1);
    lp0 += __shfl_xor_sync(0xffffffffu, lp0, 2);
    lp1 += __shfl_xor_sync(0xffffffffu, lp1, 1);
    lp1 += __shfl_xor_sync(0xffffffffu, lp1, 2);
    if (t == 0) {
        g_invl[(size_t)bh * Ss + r0]     = 1.f / lp0;
        g_invl[(size_t)bh * Ss + r0 + 8] = 1.f / lp1;
    }
}

// ===== Kernel B: read fp16 e, write normalized att (float4) + MMA2; no MMA1 =====
__global__ __launch_bounds__(256, 2)
void attn_write(const float* __restrict__ V, float* __restrict__ att,
                float* __restrict__ outv)
{
    const int bid = blockIdx.x;
    const int tid = threadIdx.x;
    extern __shared__ char smc[];
    const uint32_t smb = smem_u32(smc);
    const int w = tid >> 5;
    const int lane = tid & 31;
    const int g = lane >> 2;
    const int t = lane & 3;
    const int l15 = lane & 15;

    const int bh = bid >> 4;
    const int q0 = (bid & 15) * 128;

    const float* Vg = V + (size_t)bh * Ss * Dd;
    float* Ag = att + ((size_t)bh * Ss + q0) * Ss;        // this CTA's 128 att rows
    uint32_t* WAg = (uint32_t*)Ag;

    const int r0 = q0 + w * 16 + g;
    const float inv0 = __ldg(&g_invl[(size_t)bh * Ss + r0]);
    const float inv1 = __ldg(&g_invl[(size_t)bh * Ss + r0 + 8]);

    const uint32_t eaddr = smb + OFF_E + (uint32_t)(w * 16 + l15) * EROWB +
                           ((lane >> 4) & 1) * 16;
    const uint32_t vaddr = smb + OFF_V + (uint32_t)l15 * ROWB + ((lane >> 4) & 1) * 16;

    float o[8][4];
    #pragma unroll
    for (int i = 0; i < 8; ++i)
        #pragma unroll
        for (int j = 0; j < 4; ++j) o[i][j] = 0.f;

    // DESCENDING kt: tile reads (words [k0/2,k0/2+64)) never collide with
    // fp32 writes (words [k0,k0+128)) of this or later-processed tiles.
    for (int kt = Ss / 128 - 1; kt >= 0; --kt) {
        const int k0 = kt * 128;
        __syncthreads();
        // e tile: 128 rows x 64 words, coalesced
        for (int i = tid; i < 4096; i += 256) {
            int row = i >> 5;
            int jw = (i & 31) * 2;
            uint2 val = *(const uint2*)(WAg + (size_t)row * 2048 + (k0 >> 1) + jw);
            *(uint2*)(smc + OFF_E + row * EROWB + jw * 4) = val;
        }
        // V tile
        for (int i = tid; i < 2048; i += 256) {
            int row = i >> 4;
            int d4 = (i & 15) << 2;
            float4 u = *(const float4*)(Vg + (size_t)(k0 + row) * Dd + d4);
            *(uint2*)(smc + OFF_V + row * ROWB + d4 * 2) =
                make_uint2(pack16(u.x, u.y), pack16(u.z, u.w));
        }
        if (kt > 0) {
            prefetchL2(Vg + (size_t)(k0 - 128) * Dd + tid * 32);
            prefetchL2(WAg + ((size_t)(tid >> 1) * 2048) + ((k0 - 128) >> 1) + (tid & 1) * 32);
        }
        __syncthreads();

        for (int ch = 0; ch < 8; ++ch) {
            const int kb = ch * 16;

            // ---- P fragments straight from fp16 e plane ----
            uint32_t pe[4];
            ldsm4(pe, eaddr + kb * 2);

            // ---- att = f32(e16) * inv, repacked to float4, streamed out ----
            float2 f00 = unpack16(pe[0]);   // row g,   cols kb+2t..+1
            float2 f01 = unpack16(pe[1]);   // row g+8, cols kb+2t..+1
            float2 f10 = unpack16(pe[2]);   // row g,   cols kb+8+2t..+1
            float2 f11 = unpack16(pe[3]);   // row g+8, cols kb+8+2t..+1
            f00.x *= inv0; f00.y *= inv0; f10.x *= inv0; f10.y *= inv0;
            f01.x *= inv1; f01.y *= inv1; f11.x *= inv1; f11.y *= inv1;
            const int c4 = k0 + kb + 4 * t;
            float4 fa = repack4(f00, f10, t);
            float4 fb = repack4(f01, f11, t);
            stcs4(Ag + (size_t)(w * 16 + g) * Ss + c4, fa);
            stcs4(Ag + (size_t)(w * 16 + g + 8) * Ss + c4, fb);

            // ---- MMA2 on unnormalized e (scale O at the end) ----
            const uint32_t va = vaddr + (uint32_t)kb * ROWB;
            #pragma unroll
            for (int np = 0; np < 4; ++np) {
                uint32_t v0, v1, v2, v3;
                ldsm4t(v0, v1, v2, v3, va + np * 32);
                mma16816(o[2 * np], pe, v0, v1);
                mma16816(o[2 * np + 1], pe, v2, v3);
            }
        }
    }

    // ---- scale O by inv, store ----
    float* O0 = outv + ((size_t)bh * Ss + r0) * Dd;
    float* O1 = O0 + 8 * Dd;
    #pragma unroll
    for (int nb2 = 0; nb2 < 8; ++nb2) {
        stcs2(O0 + nb2 * 8 + 2 * t, make_float2(o[nb2][0] * inv0, o[nb2][1] * inv0));
        stcs2(O1 + nb2 * 8 + 2 * t, make_float2(o[nb2][2] * inv1, o[nb2][3] * inv1));
    }
}

extern "C" void kernel_launch(void* const* d_in, const int* in_sizes, int n_in,
                              void* d_out, int out_size)
{
    const float* Q = (const float*)d_in[0];
    const float* K = (const float*)d_in[1];
    const float* V = (const float*)d_in[2];
    const int* M = (const int*)d_in[3];

    float* att = (float*)d_out;
    float* sumv = att + (size_t)Bb * Hh * Ss * Ss;

    static int configured = 0;
    if (!configured) {
        cudaFuncSetAttribute(attn_sums, cudaFuncAttributeMaxDynamicSharedMemorySize, A_SMEM);
        cudaFuncSetAttribute(attn_write, cudaFuncAttributeMaxDynamicSharedMemorySize, B_SMEM);
        configured = 1;
    }

    attn_sums<<<Bb * Hh * 16, 256, A_SMEM>>>(Q, K, M, att);
    attn_write<<<Bb * Hh * 16, 256, B_SMEM>>>(V, att, sumv);
}